// round 12
// baseline (speedup 1.0000x reference)
#include <cuda_runtime.h>
#include <cuda_fp16.h>

#define NBX 168
#define NBY 480
#define NBL 6
#define NBXP 172                      // x index range: bx0+2+i in [0,172)
#define NYS 62                        // ys index range (slot/8 + 1) in [0,61]
#define WW 5
#define NREP 2                        // fp16 accumulation replicas
#define CELLS (2 * NBL * NYS * NBXP)  // 127968 cells (var,t,ys,x)
#define NDEM2 (CELLS * 8)             // 1023744 halfs (~2MB)
#define NPLANE (NYS * NBXP)           // 10664
#define TABK 256                      // weight table resolution
#define TABN ((TABK + 1) * 5)         // 1285 floats
#define INV_SQRT2 0.70710678118654752440f
#define INV_CAP (1.0f / 16.0f)

// Cell (var,t,ys,x) holds 8 halfs covering absolute y = y4 + k.
#define OFFC(var, t, ys, x) \
    ((((((var) * NBL) + (t)) * NYS + (ys)) * NBXP + (x)) * 8)

__device__ __align__(16) float  g_tab[TABN];
__device__ __align__(16) __half g_dem2[NREP][NDEM2];
__device__ __align__(16) __half g_compat2[NDEM2];

__device__ __forceinline__ void red_add_v4h2(__half* addr, __half2 a, __half2 b,
                                             __half2 c, __half2 d) {
    unsigned ua = *(unsigned*)&a, ub = *(unsigned*)&b;
    unsigned uc = *(unsigned*)&c, ud = *(unsigned*)&d;
    asm volatile("red.global.add.noftz.v4.f16x2 [%0], {%1, %2, %3, %4};"
                 :: "l"(addr), "r"(ua), "r"(ub), "r"(uc), "r"(ud) : "memory");
}

// ---------------------------------------------------------------------------
// Phase 0: build the weight table. g_k(frac), frac = c - floor(c):
//   g_k = 0.5*(erf((k-1-frac)/sqrt2) - erf((k-2-frac)/sqrt2)), k = 0..4
// ---------------------------------------------------------------------------
__global__ void table_kernel() {
    int j = blockIdx.x * blockDim.x + threadIdx.x;
    if (j > TABK) return;
    float frac = (float)j / (float)TABK;
    float ep = erff((-2.0f - frac) * INV_SQRT2);
#pragma unroll
    for (int k = 0; k < WW; k++) {
        float e = erff(((float)(k - 1) - frac) * INV_SQRT2);
        g_tab[j * 5 + k] = 0.5f * (e - ep);
        ep = e;
    }
}

// Stage the table into shared memory (5.1KB).
__device__ __forceinline__ void load_tab(float* s_tab) {
    for (int i = threadIdx.x; i < TABN; i += blockDim.x)
        s_tab[i] = g_tab[i];
    __syncthreads();
}

// Axis weights via table + lerp: 10 LDS + 5 FMA, zero MUFU.
__device__ __forceinline__ void axis_w(const float* __restrict__ s_tab,
                                       float c, int& b0, float* g) {
    float fl = floorf(c);
    b0 = (int)fl - 2;
    float u = (c - fl) * (float)TABK;
    float ju = floorf(u);
    float t = u - ju;
    int j = (int)ju * 5;
#pragma unroll
    for (int k = 0; k < WW; k++) {
        float a = s_tab[j + k];
        float b = s_tab[j + 5 + k];
        g[k] = fmaf(b - a, t, a);
    }
}

// Place g[0..4] at slots m..m+4 of an 8-wide window (m in 0..3), zeros
// elsewhere. Pure predicated selects, no dynamic indexing.
__device__ __forceinline__ void place_y(const float* g, int m, float* w) {
#pragma unroll
    for (int s = 0; s < 8; s++) w[s] = 0.0f;
#pragma unroll
    for (int k = 0; k < WW; k++) {
#pragma unroll
        for (int mm = 0; mm < 4; mm++)
            w[k + mm] = (m == mm) ? g[k] : w[k + mm];
    }
}

// ---------------------------------------------------------------------------
// Phase 1: scatter — 5 v4.f16x2 REDs per instance to contiguous 16B cells.
// ---------------------------------------------------------------------------
__global__ void scatter_kernel(const float* __restrict__ pos,
                               const float* __restrict__ nsx,
                               const float* __restrict__ nsy,
                               const int*   __restrict__ lidx,
                               const int*   __restrict__ ltype,
                               int Lnum, int n) {
    __shared__ float s_tab[TABN];
    load_tab(s_tab);

    int l = blockIdx.x * blockDim.x + threadIdx.x;
    if (l >= Lnum) return;
    int idx = lidx[l];
    float sx = nsx[idx];
    float sy = nsy[idx];
    float cx = pos[idx]     + 0.5f * sx;
    float cy = pos[n + idx] + 0.5f * sy;
    float area = sx * sy;
    int lt = ltype[idx];
    int rep = l & (NREP - 1);

    int bx0, b0y;
    float gx[WW], gy[WW], wy[8];
    axis_w(s_tab, cx, bx0, gx);
    axis_w(s_tab, cy, b0y, gy);
    int y4 = b0y & ~3;
    place_y(gy, b0y - y4, wy);

    __half2 hwy[4];
    hwy[0] = __floats2half2_rn(wy[0], wy[1]);
    hwy[1] = __floats2half2_rn(wy[2], wy[3]);
    hwy[2] = __floats2half2_rn(wy[4], wy[5]);
    hwy[3] = __floats2half2_rn(wy[6], wy[7]);

    int var   = (y4 >> 2) & 1;
    int slot  = y4 - 4 * var;         // multiple of 8, may be -8
    int ysIdx = slot / 8 + 1;         // [0, 60]
    __half* base = g_dem2[rep] + OFFC(var, lt, ysIdx, bx0 + 2);

#pragma unroll
    for (int i = 0; i < WW; i++) {
        __half2 a2 = __half2half2(__float2half_rn(area * gx[i]));
        red_add_v4h2(base + i * 8,
                     __hmul2(a2, hwy[0]), __hmul2(a2, hwy[1]),
                     __hmul2(a2, hwy[2]), __hmul2(a2, hwy[3]));
    }
}

// ---------------------------------------------------------------------------
// Phase 2: compat (thread per (ys,x) for p < NPLANE) + output zeroing spread
// across the whole (wide) grid. Compat threads also re-zero the A-cells they
// exclusively read (re-arming them for the next replay).
// ---------------------------------------------------------------------------
__global__ void compat_kernel(const int* __restrict__ frac,
                              float* __restrict__ out, int osz) {
    int p = blockIdx.x * blockDim.x + threadIdx.x;
    int nt = gridDim.x * blockDim.x;
    for (int i = p; i * 2 + 1 < osz; i += nt)
        ((float2*)out)[i] = make_float2(0.0f, 0.0f);
    if (p == 0 && (osz & 1)) out[osz - 1] = 0.0f;

    if (p >= NPLANE) return;
    int ysIdx = p / NBXP;
    int x = p - ysIdx * NBXP;

    float ff[NBL][NBL];
#pragma unroll
    for (int t = 0; t < NBL; t++)
#pragma unroll
        for (int l = 0; l < NBL; l++)
            ff[t][l] = (float)__ldg(&frac[t * NBL + l]);

    float s[NBL][8];
#pragma unroll
    for (int t = 0; t < NBL; t++)
#pragma unroll
        for (int k = 0; k < 8; k++) s[t][k] = 0.0f;

    const uint4 zero4 = make_uint4(0u, 0u, 0u, 0u);

#pragma unroll
    for (int l = 0; l < NBL; l++) {
        float d8[8];
#pragma unroll
        for (int k = 0; k < 8; k++) d8[k] = 0.0f;
#pragma unroll
        for (int r = 0; r < NREP; r++) {
            uint4 va = *(const uint4*)&g_dem2[r][OFFC(0, l, ysIdx, x)];
            *(uint4*)&g_dem2[r][OFFC(0, l, ysIdx, x)] = zero4;
            float2 f;
            f = __half22float2(*(const __half2*)&va.x); d8[0] += f.x; d8[1] += f.y;
            f = __half22float2(*(const __half2*)&va.y); d8[2] += f.x; d8[3] += f.y;
            f = __half22float2(*(const __half2*)&va.z); d8[4] += f.x; d8[5] += f.y;
            f = __half22float2(*(const __half2*)&va.w); d8[6] += f.x; d8[7] += f.y;
            uint4 vb = *(const uint4*)&g_dem2[r][OFFC(1, l, ysIdx, x)];
            f = __half22float2(*(const __half2*)&vb.x); d8[4] += f.x; d8[5] += f.y;
            f = __half22float2(*(const __half2*)&vb.y); d8[6] += f.x; d8[7] += f.y;
            if (ysIdx > 0) {
                uint4 vp = *(const uint4*)&g_dem2[r][OFFC(1, l, ysIdx - 1, x)];
                f = __half22float2(*(const __half2*)&vp.z); d8[0] += f.x; d8[1] += f.y;
                f = __half22float2(*(const __half2*)&vp.w); d8[2] += f.x; d8[3] += f.y;
            }
        }
#pragma unroll
        for (int t = 0; t < NBL; t++) {
            float f = ff[t][l];
#pragma unroll
            for (int k = 0; k < 8; k++)
                s[t][k] = fmaf(f, d8[k], s[t][k]);
        }
    }

#pragma unroll
    for (int t = 0; t < NBL; t++) {
        __half2 h0 = __floats2half2_rn(s[t][0], s[t][1]);
        __half2 h1 = __floats2half2_rn(s[t][2], s[t][3]);
        __half2 h2 = __floats2half2_rn(s[t][4], s[t][5]);
        __half2 h3 = __floats2half2_rn(s[t][6], s[t][7]);
        uint4 o;
        o.x = *(unsigned*)&h0; o.y = *(unsigned*)&h1;
        o.z = *(unsigned*)&h2; o.w = *(unsigned*)&h3;
        *(uint4*)&g_compat2[OFFC(0, t, ysIdx, x)] = o;
        uint2 lo; lo.x = o.z; lo.y = o.w;
        *(uint2*)&g_compat2[OFFC(1, t, ysIdx, x)] = lo;
        if (ysIdx > 0) {
            uint2 hi; hi.x = o.x; hi.y = o.y;
            *(uint2*)&g_compat2[OFFC(1, t, ysIdx - 1, x) + 4] = hi;
        }
    }
}

// ---------------------------------------------------------------------------
// Phase 3: gather — 5 contiguous LDG.128 + dot, table weights. Zeroes only
// the B-cells (A-cells were re-armed inside compat).
// ---------------------------------------------------------------------------
__global__ void gather_kernel(const float* __restrict__ pos,
                              const float* __restrict__ nsx,
                              const float* __restrict__ nsy,
                              const int*   __restrict__ lidx,
                              const int*   __restrict__ ltype,
                              float* __restrict__ out,
                              int Lnum, int n) {
    __shared__ float s_tab[TABN];
    load_tab(s_tab);

    int l = blockIdx.x * blockDim.x + threadIdx.x;
    int nt = gridDim.x * blockDim.x;
    const int NZB = (NDEM2 / 2) / 8;        // uint4 count per replica B-region
    for (int i = l; i < NREP * NZB; i += nt) {
        int r = i / NZB;
        int j = i - r * NZB;
        ((uint4*)(g_dem2[r] + NDEM2 / 2))[j] = make_uint4(0u, 0u, 0u, 0u);
    }

    if (l >= Lnum) return;
    int idx = lidx[l];
    float sx = nsx[idx];
    float sy = nsy[idx];
    float cx = pos[idx]     + 0.5f * sx;
    float cy = pos[n + idx] + 0.5f * sy;
    int lt = ltype[idx];

    int bx0, b0y;
    float gx[WW], gy[WW], wy[8];
    axis_w(s_tab, cx, bx0, gx);
    axis_w(s_tab, cy, b0y, gy);
    int y4 = b0y & ~3;
    place_y(gy, b0y - y4, wy);

    // Range masks (reference semantics: OOB bins contribute nothing).
#pragma unroll
    for (int s = 0; s < 8; s++)
        if ((unsigned)(y4 + s) >= (unsigned)NBY) wy[s] = 0.0f;
#pragma unroll
    for (int i = 0; i < WW; i++)
        if ((unsigned)(bx0 + i) >= (unsigned)NBX) gx[i] = 0.0f;

    int var   = (y4 >> 2) & 1;
    int slot  = y4 - 4 * var;
    int ysIdx = slot / 8 + 1;
    const __half* base = g_compat2 + OFFC(var, lt, ysIdx, bx0 + 2);

    uint4 v[WW];
#pragma unroll
    for (int i = 0; i < WW; i++)
        v[i] = *(const uint4*)(base + i * 8);

    float s = 0.0f;
#pragma unroll
    for (int i = 0; i < WW; i++) {
        float2 c0 = __half22float2(*(const __half2*)&v[i].x);
        float2 c1 = __half22float2(*(const __half2*)&v[i].y);
        float2 c2 = __half22float2(*(const __half2*)&v[i].z);
        float2 c3 = __half22float2(*(const __half2*)&v[i].w);
        float sj = c0.x * wy[0] + c0.y * wy[1] + c1.x * wy[2] + c1.y * wy[3]
                 + c2.x * wy[4] + c2.y * wy[5] + c3.x * wy[6] + c3.y * wy[7];
        s += gx[i] * sj;
    }
    out[idx] = s * INV_CAP;
}

// ---------------------------------------------------------------------------
extern "C" void kernel_launch(void* const* d_in, const int* in_sizes, int n_in,
                              void* d_out, int out_size) {
    const float* pos   = (const float*)d_in[0];
    const float* nsx   = (const float*)d_in[1];
    const float* nsy   = (const float*)d_in[2];
    const int*   lidx  = (const int*)d_in[3];
    const int*   ltype = (const int*)d_in[4];
    const int*   frac  = (const int*)d_in[5];
    float* out = (float*)d_out;

    int n    = in_sizes[1];   // number of nodes (2M)
    int Lnum = in_sizes[3];   // number of instances (1M)

    table_kernel<<<2, 160>>>();
    scatter_kernel<<<(Lnum + 255) / 256, 256>>>(pos, nsx, nsy, lidx, ltype,
                                                Lnum, n);
    compat_kernel<<<2048, 256>>>(frac, out, out_size);
    gather_kernel<<<(Lnum + 255) / 256, 256>>>(pos, nsx, nsy, lidx, ltype,
                                               out, Lnum, n);
}

// round 13
// speedup vs baseline: 1.1606x; 1.1606x over previous
#include <cuda_runtime.h>
#include <cuda_fp16.h>

#define NBX 168
#define NBY 480
#define NBL 6
#define NBXP 172                      // x index range: bx0+2+i in [0,172)
#define NYS 62                        // ys index range (slot/8 + 1) in [0,61]
#define WW 5
#define NREP 2                        // fp16 accumulation replicas
#define CELLS (2 * NBL * NYS * NBXP)  // 127968 cells (var,t,ys,x)
#define NDEM2 (CELLS * 8)             // 1023744 halfs (~2MB)
#define NPLANE (NYS * NBXP)           // 10664
#define INV_SQRT2 0.70710678118654752440f
#define INV_CAP (1.0f / 16.0f)

// Cell (var,t,ys,x) holds 8 halfs covering absolute y = y4 + k.
#define OFFC(var, t, ys, x) \
    ((((((var) * NBL) + (t)) * NYS + (ys)) * NBXP + (x)) * 8)

__device__ __align__(16) __half g_dem2[NREP][NDEM2];
__device__ __align__(16) __half g_compat2[NDEM2];

__device__ __forceinline__ void red_add_v4h2(__half* addr, __half2 a, __half2 b,
                                             __half2 c, __half2 d) {
    unsigned ua = *(unsigned*)&a, ub = *(unsigned*)&b;
    unsigned uc = *(unsigned*)&c, ud = *(unsigned*)&d;
    asm volatile("red.global.add.noftz.v4.f16x2 [%0], {%1, %2, %3, %4};"
                 :: "l"(addr), "r"(ua), "r"(ub), "r"(uc), "r"(ud) : "memory");
}

// Fast erf (Abramowitz-Stegun 7.1.26, |abs err| <= 1.5e-7): 2 MUFU + ~9 FMA.
__device__ __forceinline__ float erf_fast(float x) {
    float ax = fabsf(x);
    float t = __fdividef(1.0f, fmaf(0.3275911f, ax, 1.0f));
    float e = __expf(-ax * ax);
    float q = fmaf(1.061405429f, t, -1.453152027f);
    q = fmaf(q, t, 1.421413741f);
    q = fmaf(q, t, -0.284496736f);
    q = fmaf(q, t, 0.254829592f);
    float r = fmaf(-q * t, e, 1.0f);
    return copysignf(r, x);
}

// 5 window weights via a 6-erf chain (no range mask).
__device__ __forceinline__ void w5(float c, int& b0, float* g) {
    b0 = (int)floorf(c) - 2;
    float ep = erf_fast(((float)b0 - c) * INV_SQRT2);
#pragma unroll
    for (int k = 0; k < WW; k++) {
        float e = erf_fast(((float)(b0 + k + 1) - c) * INV_SQRT2);
        g[k] = 0.5f * (e - ep);
        ep = e;
    }
}

// Place g[0..4] at slots m..m+4 of an 8-wide window (m in 0..3), zeros
// elsewhere. Pure predicated selects, no dynamic indexing, no MUFU/LDS.
__device__ __forceinline__ void place_y(const float* g, int m, float* w) {
#pragma unroll
    for (int s = 0; s < 8; s++) w[s] = 0.0f;
#pragma unroll
    for (int k = 0; k < WW; k++) {
#pragma unroll
        for (int mm = 0; mm < 4; mm++)
            w[k + mm] = (m == mm) ? g[k] : w[k + mm];
    }
}

// ---------------------------------------------------------------------------
// Phase 1: scatter — 5 v4.f16x2 REDs per instance to contiguous 16B cells.
// ---------------------------------------------------------------------------
__global__ void scatter_kernel(const float* __restrict__ pos,
                               const float* __restrict__ nsx,
                               const float* __restrict__ nsy,
                               const int*   __restrict__ lidx,
                               const int*   __restrict__ ltype,
                               int Lnum, int n) {
    int l = blockIdx.x * blockDim.x + threadIdx.x;
    if (l >= Lnum) return;
    int idx = lidx[l];
    float sx = nsx[idx];
    float sy = nsy[idx];
    float cx = pos[idx]     + 0.5f * sx;
    float cy = pos[n + idx] + 0.5f * sy;
    float area = sx * sy;
    int lt = ltype[idx];
    int rep = l & (NREP - 1);

    int bx0, b0y;
    float gx[WW], gy[WW], wy[8];
    w5(cx, bx0, gx);
    w5(cy, b0y, gy);
    int y4 = b0y & ~3;
    place_y(gy, b0y - y4, wy);

    __half2 hwy[4];
    hwy[0] = __floats2half2_rn(wy[0], wy[1]);
    hwy[1] = __floats2half2_rn(wy[2], wy[3]);
    hwy[2] = __floats2half2_rn(wy[4], wy[5]);
    hwy[3] = __floats2half2_rn(wy[6], wy[7]);

    int var   = (y4 >> 2) & 1;
    int slot  = y4 - 4 * var;         // multiple of 8, may be -8
    int ysIdx = slot / 8 + 1;         // [0, 60]
    __half* base = g_dem2[rep] + OFFC(var, lt, ysIdx, bx0 + 2);

#pragma unroll
    for (int i = 0; i < WW; i++) {
        __half2 a2 = __half2half2(__float2half_rn(area * gx[i]));
        red_add_v4h2(base + i * 8,
                     __hmul2(a2, hwy[0]), __hmul2(a2, hwy[1]),
                     __hmul2(a2, hwy[2]), __hmul2(a2, hwy[3]));
    }
}

// ---------------------------------------------------------------------------
// Phase 2: compat (thread per (ys,x) for p < NPLANE) + output zeroing spread
// across the whole (wide) grid. Compat threads also re-zero the A-cells they
// exclusively read (re-arming them for the next replay).
// ---------------------------------------------------------------------------
__global__ void compat_kernel(const int* __restrict__ frac,
                              float* __restrict__ out, int osz) {
    int p = blockIdx.x * blockDim.x + threadIdx.x;
    int nt = gridDim.x * blockDim.x;
    for (int i = p; i * 2 + 1 < osz; i += nt)
        ((float2*)out)[i] = make_float2(0.0f, 0.0f);
    if (p == 0 && (osz & 1)) out[osz - 1] = 0.0f;

    if (p >= NPLANE) return;
    int ysIdx = p / NBXP;
    int x = p - ysIdx * NBXP;

    float ff[NBL][NBL];
#pragma unroll
    for (int t = 0; t < NBL; t++)
#pragma unroll
        for (int l = 0; l < NBL; l++)
            ff[t][l] = (float)__ldg(&frac[t * NBL + l]);

    float s[NBL][8];
#pragma unroll
    for (int t = 0; t < NBL; t++)
#pragma unroll
        for (int k = 0; k < 8; k++) s[t][k] = 0.0f;

    const uint4 zero4 = make_uint4(0u, 0u, 0u, 0u);

#pragma unroll
    for (int l = 0; l < NBL; l++) {
        float d8[8];
#pragma unroll
        for (int k = 0; k < 8; k++) d8[k] = 0.0f;
#pragma unroll
        for (int r = 0; r < NREP; r++) {
            uint4 va = *(const uint4*)&g_dem2[r][OFFC(0, l, ysIdx, x)];
            *(uint4*)&g_dem2[r][OFFC(0, l, ysIdx, x)] = zero4;
            float2 f;
            f = __half22float2(*(const __half2*)&va.x); d8[0] += f.x; d8[1] += f.y;
            f = __half22float2(*(const __half2*)&va.y); d8[2] += f.x; d8[3] += f.y;
            f = __half22float2(*(const __half2*)&va.z); d8[4] += f.x; d8[5] += f.y;
            f = __half22float2(*(const __half2*)&va.w); d8[6] += f.x; d8[7] += f.y;
            uint4 vb = *(const uint4*)&g_dem2[r][OFFC(1, l, ysIdx, x)];
            f = __half22float2(*(const __half2*)&vb.x); d8[4] += f.x; d8[5] += f.y;
            f = __half22float2(*(const __half2*)&vb.y); d8[6] += f.x; d8[7] += f.y;
            if (ysIdx > 0) {
                uint4 vp = *(const uint4*)&g_dem2[r][OFFC(1, l, ysIdx - 1, x)];
                f = __half22float2(*(const __half2*)&vp.z); d8[0] += f.x; d8[1] += f.y;
                f = __half22float2(*(const __half2*)&vp.w); d8[2] += f.x; d8[3] += f.y;
            }
        }
#pragma unroll
        for (int t = 0; t < NBL; t++) {
            float f = ff[t][l];
#pragma unroll
            for (int k = 0; k < 8; k++)
                s[t][k] = fmaf(f, d8[k], s[t][k]);
        }
    }

#pragma unroll
    for (int t = 0; t < NBL; t++) {
        __half2 h0 = __floats2half2_rn(s[t][0], s[t][1]);
        __half2 h1 = __floats2half2_rn(s[t][2], s[t][3]);
        __half2 h2 = __floats2half2_rn(s[t][4], s[t][5]);
        __half2 h3 = __floats2half2_rn(s[t][6], s[t][7]);
        uint4 o;
        o.x = *(unsigned*)&h0; o.y = *(unsigned*)&h1;
        o.z = *(unsigned*)&h2; o.w = *(unsigned*)&h3;
        *(uint4*)&g_compat2[OFFC(0, t, ysIdx, x)] = o;
        uint2 lo; lo.x = o.z; lo.y = o.w;
        *(uint2*)&g_compat2[OFFC(1, t, ysIdx, x)] = lo;
        if (ysIdx > 0) {
            uint2 hi; hi.x = o.x; hi.y = o.y;
            *(uint2*)&g_compat2[OFFC(1, t, ysIdx - 1, x) + 4] = hi;
        }
    }
}

// ---------------------------------------------------------------------------
// Phase 3: gather — 5 contiguous LDG.128 + dot. Zeroes only the B-cells
// (A-cells were re-armed inside compat).
// ---------------------------------------------------------------------------
__global__ void gather_kernel(const float* __restrict__ pos,
                              const float* __restrict__ nsx,
                              const float* __restrict__ nsy,
                              const int*   __restrict__ lidx,
                              const int*   __restrict__ ltype,
                              float* __restrict__ out,
                              int Lnum, int n) {
    int l = blockIdx.x * blockDim.x + threadIdx.x;
    int nt = gridDim.x * blockDim.x;
    const int NZB = (NDEM2 / 2) / 8;        // uint4 count per replica B-region
    for (int i = l; i < NREP * NZB; i += nt) {
        int r = i / NZB;
        int j = i - r * NZB;
        ((uint4*)(g_dem2[r] + NDEM2 / 2))[j] = make_uint4(0u, 0u, 0u, 0u);
    }

    if (l >= Lnum) return;
    int idx = lidx[l];
    float sx = nsx[idx];
    float sy = nsy[idx];
    float cx = pos[idx]     + 0.5f * sx;
    float cy = pos[n + idx] + 0.5f * sy;
    int lt = ltype[idx];

    int bx0, b0y;
    float gx[WW], gy[WW], wy[8];
    w5(cx, bx0, gx);
    w5(cy, b0y, gy);
    int y4 = b0y & ~3;
    place_y(gy, b0y - y4, wy);

    // Range masks (reference semantics: OOB bins contribute nothing).
#pragma unroll
    for (int s = 0; s < 8; s++)
        if ((unsigned)(y4 + s) >= (unsigned)NBY) wy[s] = 0.0f;
#pragma unroll
    for (int i = 0; i < WW; i++)
        if ((unsigned)(bx0 + i) >= (unsigned)NBX) gx[i] = 0.0f;

    int var   = (y4 >> 2) & 1;
    int slot  = y4 - 4 * var;
    int ysIdx = slot / 8 + 1;
    const __half* base = g_compat2 + OFFC(var, lt, ysIdx, bx0 + 2);

    uint4 v[WW];
#pragma unroll
    for (int i = 0; i < WW; i++)
        v[i] = *(const uint4*)(base + i * 8);

    float s = 0.0f;
#pragma unroll
    for (int i = 0; i < WW; i++) {
        float2 c0 = __half22float2(*(const __half2*)&v[i].x);
        float2 c1 = __half22float2(*(const __half2*)&v[i].y);
        float2 c2 = __half22float2(*(const __half2*)&v[i].z);
        float2 c3 = __half22float2(*(const __half2*)&v[i].w);
        float sj = c0.x * wy[0] + c0.y * wy[1] + c1.x * wy[2] + c1.y * wy[3]
                 + c2.x * wy[4] + c2.y * wy[5] + c3.x * wy[6] + c3.y * wy[7];
        s += gx[i] * sj;
    }
    out[idx] = s * INV_CAP;
}

// ---------------------------------------------------------------------------
extern "C" void kernel_launch(void* const* d_in, const int* in_sizes, int n_in,
                              void* d_out, int out_size) {
    const float* pos   = (const float*)d_in[0];
    const float* nsx   = (const float*)d_in[1];
    const float* nsy   = (const float*)d_in[2];
    const int*   lidx  = (const int*)d_in[3];
    const int*   ltype = (const int*)d_in[4];
    const int*   frac  = (const int*)d_in[5];
    float* out = (float*)d_out;

    int n    = in_sizes[1];   // number of nodes (2M)
    int Lnum = in_sizes[3];   // number of instances (1M)

    scatter_kernel<<<(Lnum + 255) / 256, 256>>>(pos, nsx, nsy, lidx, ltype,
                                                Lnum, n);
    compat_kernel<<<2048, 256>>>(frac, out, out_size);
    gather_kernel<<<(Lnum + 255) / 256, 256>>>(pos, nsx, nsy, lidx, ltype,
                                               out, Lnum, n);
}